// round 3
// baseline (speedup 1.0000x reference)
#include <cuda_runtime.h>
#include <math.h>

// Problem constants
#define T_STEPS 200
#define BATCH   1024
#define XD      48
#define AD      15
#define IN_DIM  64      // XD + AD + 1
#define H_DIM   512
#define G4      2048    // 4*H
#define KTOT    576     // IN_DIM + H_DIM
#define OUT_DIM 32
#define H1      513     // H + 1

// Scratch (static device allocations only; no cudaMalloc anywhere)
__device__ float g_h[2][BATCH * H_DIM];   // double-buffered hidden state
__device__ float g_c[BATCH * H_DIM];      // cell state (tile-private, single buffer)
__device__ float g_z1[2][BATCH * H1];     // hidden of the two MLP heads
__device__ float g_maxm;

// ---------------------------------------------------------------------------
// Init: zero h[0] and c
// ---------------------------------------------------------------------------
__global__ __launch_bounds__(256) void zero_kernel() {
    int idx = blockIdx.x * blockDim.x + threadIdx.x;
    int stride = gridDim.x * blockDim.x;
    for (int i = idx; i < BATCH * H_DIM; i += stride) {
        g_h[0][i] = 0.0f;
        g_c[i]    = 0.0f;
    }
}

// ---------------------------------------------------------------------------
// max(m) over T*B elements — single CTA
// ---------------------------------------------------------------------------
__global__ __launch_bounds__(256) void maxm_kernel(const float* __restrict__ m) {
    __shared__ float red[256];
    float v = -1e30f;
    for (int i = threadIdx.x; i < T_STEPS * BATCH; i += 256)
        v = fmaxf(v, m[i]);
    red[threadIdx.x] = v;
    __syncthreads();
    for (int s = 128; s > 0; s >>= 1) {
        if (threadIdx.x < s) red[threadIdx.x] = fmaxf(red[threadIdx.x], red[threadIdx.x + s]);
        __syncthreads();
    }
    if (threadIdx.x == 0) g_maxm = red[0];
}

// ---------------------------------------------------------------------------
// Fused LSTM step: gates = x_in @ w_ih^T + h @ w_hh^T + (b_ih + b_hh),
// then cell update. CTA tile: 64 batch rows x 32 h-cols x all 4 gates
// (n_local = gate*32 + hc, 128 gate columns). One barrier-free fusion:
// i/f/g/o for a given (b,hc) live in the same thread's registers.
// ---------------------------------------------------------------------------
#define KC  32
#define SIS 65    // sIn row stride (conflict-free)
#define SWS 129   // sW row stride (conflict-free)

__global__ __launch_bounds__(256) void step_kernel(
    const float* __restrict__ x, const float* __restrict__ a,
    const float* __restrict__ w_ih, const float* __restrict__ w_hh,
    const float* __restrict__ b_ih, const float* __restrict__ b_hh,
    int s)
{
    __shared__ float sIn[KC * SIS];   // [k][b]  64 batch
    __shared__ float sW[KC * SWS];    // [k][n]  128 gate cols

    const int hT = blockIdx.x;            // 0..15  (32 h-cols each)
    const int bT = blockIdx.y;            // 0..15  (64 batch rows each)
    const int b0 = bT * 64;
    const int h0 = hT * 32;
    const int tid = threadIdx.x;
    const int tx = tid & 15;              // -> gate cols tx + 16*j
    const int ty = tid >> 4;              // -> batch rows ty + 16*i

    const float* __restrict__ hbuf = g_h[s & 1];
    float* __restrict__ hout       = g_h[(s + 1) & 1];
    const int trow = T_STEPS - 1 - s;     // flipped sequence index
    const float tval = (float)s / g_maxm;

    // Biases for this thread's 8 gate columns: n = gate*512 + h0 + tx + 16*m, j = 2*gate + m
    float bsum[8];
#pragma unroll
    for (int j = 0; j < 8; j++) {
        int n = (j >> 1) * H_DIM + h0 + tx + 16 * (j & 1);
        bsum[j] = b_ih[n] + b_hh[n];
    }

    float acc[4][8];
#pragma unroll
    for (int i = 0; i < 4; i++)
#pragma unroll
        for (int j = 0; j < 8; j++) acc[i][j] = 0.0f;

    for (int k0 = 0; k0 < KTOT; k0 += KC) {
        // Stage input tile [KC x 64]: warp lanes sweep kk (coalesced, conflict-free)
#pragma unroll
        for (int i = 0; i < 8; i++) {
            int lin = tid + i * 256;
            int kk = lin & 31, bb = lin >> 5;
            int kG = k0 + kk;
            int b = b0 + bb;
            float v;
            if (kG >= IN_DIM)           v = hbuf[b * H_DIM + (kG - IN_DIM)];
            else if (kG < XD)           v = x[(size_t)trow * BATCH * XD + b * XD + kG];
            else if (kG < XD + AD)      v = a[(size_t)trow * BATCH * AD + b * AD + (kG - XD)];
            else                        v = tval;
            sIn[kk * SIS + bb] = v;
        }
        // Stage weight tile [KC x 128]
#pragma unroll
        for (int i = 0; i < 16; i++) {
            int lin = tid + i * 256;
            int kk = lin & 31, nn = lin >> 5;
            int gate = nn >> 5, hc = nn & 31;
            int row = gate * H_DIM + h0 + hc;
            int kG = k0 + kk;
            float w = (kG < IN_DIM) ? w_ih[row * IN_DIM + kG]
                                    : w_hh[row * H_DIM + (kG - IN_DIM)];
            sW[kk * SWS + nn] = w;
        }
        __syncthreads();

#pragma unroll
        for (int k = 0; k < KC; k++) {
            float rIn[4], rW[8];
#pragma unroll
            for (int i = 0; i < 4; i++) rIn[i] = sIn[k * SIS + ty + 16 * i];
#pragma unroll
            for (int j = 0; j < 8; j++) rW[j] = sW[k * SWS + tx + 16 * j];
#pragma unroll
            for (int i = 0; i < 4; i++)
#pragma unroll
                for (int j = 0; j < 8; j++)
                    acc[i][j] += rIn[i] * rW[j];
        }
        __syncthreads();
    }

    // LSTM cell update — this thread owns gates (i,f,g,o) for rows b0+ty+16i,
    // h-cols h0+tx+16m:  gate index j = 2*gate + m.
#pragma unroll
    for (int i = 0; i < 4; i++) {
        int b = b0 + ty + 16 * i;
#pragma unroll
        for (int mm = 0; mm < 2; mm++) {
            int hc = h0 + tx + 16 * mm;
            float iv = acc[i][0 + mm] + bsum[0 + mm];
            float fv = acc[i][2 + mm] + bsum[2 + mm];
            float gv = acc[i][4 + mm] + bsum[4 + mm];
            float ov = acc[i][6 + mm] + bsum[6 + mm];
            iv = 1.0f / (1.0f + expf(-iv));
            fv = 1.0f / (1.0f + expf(-fv));
            ov = 1.0f / (1.0f + expf(-ov));
            gv = tanhf(gv);
            int idx = b * H_DIM + hc;
            float c = fv * g_c[idx] + iv * gv;
            g_c[idx] = c;
            hout[idx] = ov * tanhf(c);
        }
    }
}

// ---------------------------------------------------------------------------
// MLP layer 1: z1 = tanh(h_final @ w1^T + b1), two heads. M=1024, N=513, K=512.
// 64x64 tile, thread 4x4 microtile.
// ---------------------------------------------------------------------------
__global__ __launch_bounds__(256) void mlp1_kernel(
    const float* __restrict__ lw1, const float* __restrict__ lb1,
    const float* __restrict__ vw1, const float* __restrict__ vb1)
{
    __shared__ float sA[KC * SIS];       // [k][b]  64
    __shared__ float sW[KC * SIS];       // [k][n]  64 (same stride works)

    const int head = blockIdx.z;
    const float* __restrict__ w  = head ? vw1 : lw1;
    const float* __restrict__ b1 = head ? vb1 : lb1;
    const float* __restrict__ A  = g_h[0];        // s=199 wrote buffer 0
    float* __restrict__ z1 = g_z1[head];

    const int n0 = blockIdx.x * 64;
    const int b0 = blockIdx.y * 64;
    const int tid = threadIdx.x;
    const int tx = tid & 15, ty = tid >> 4;

    float acc[4][4];
#pragma unroll
    for (int i = 0; i < 4; i++)
#pragma unroll
        for (int j = 0; j < 4; j++) acc[i][j] = 0.0f;

    for (int k0 = 0; k0 < H_DIM; k0 += KC) {
#pragma unroll
        for (int i = 0; i < 8; i++) {
            int lin = tid + i * 256;
            int kk = lin & 31, bb = lin >> 5;
            sA[kk * SIS + bb] = A[(b0 + bb) * H_DIM + k0 + kk];
        }
#pragma unroll
        for (int i = 0; i < 8; i++) {
            int lin = tid + i * 256;
            int kk = lin & 31, nn = lin >> 5;
            int n = n0 + nn;
            sW[kk * SIS + nn] = (n < H1) ? w[n * H_DIM + k0 + kk] : 0.0f;
        }
        __syncthreads();
#pragma unroll
        for (int k = 0; k < KC; k++) {
            float rA[4], rW[4];
#pragma unroll
            for (int i = 0; i < 4; i++) rA[i] = sA[k * SIS + ty + 16 * i];
#pragma unroll
            for (int j = 0; j < 4; j++) rW[j] = sW[k * SIS + tx + 16 * j];
#pragma unroll
            for (int i = 0; i < 4; i++)
#pragma unroll
                for (int j = 0; j < 4; j++)
                    acc[i][j] += rA[i] * rW[j];
        }
        __syncthreads();
    }

#pragma unroll
    for (int j = 0; j < 4; j++) {
        int n = n0 + tx + 16 * j;
        if (n < H1) {
            float bv = b1[n];
#pragma unroll
            for (int i = 0; i < 4; i++) {
                int b = b0 + ty + 16 * i;
                z1[b * H1 + n] = tanhf(acc[i][j] + bv);
            }
        }
    }
}

// ---------------------------------------------------------------------------
// MLP layer 2: out = tanh(z1 @ w2^T + b2), two heads. M=1024, N=32, K=513.
// Block: 32 batch rows; thread = (o, row-group), smem-staged operands.
// ---------------------------------------------------------------------------
__global__ __launch_bounds__(256) void mlp2_kernel(
    const float* __restrict__ lw2, const float* __restrict__ lb2,
    const float* __restrict__ vw2, const float* __restrict__ vb2,
    float* __restrict__ out)
{
    __shared__ float z1s[32 * 65];  // [row][kk]
    __shared__ float w2s[32 * 65];  // [o][kk]

    const int head = blockIdx.y;
    const float* __restrict__ w2 = head ? vw2 : lw2;
    const float* __restrict__ b2 = head ? vb2 : lb2;
    const float* __restrict__ z1 = g_z1[head];

    const int r0 = blockIdx.x * 32;
    const int tid = threadIdx.x;
    const int o  = tid & 31;
    const int rg = tid >> 5;        // 0..7 -> rows rg*4 .. rg*4+3

    float acc[4] = {0.f, 0.f, 0.f, 0.f};

    for (int k0 = 0; k0 < H1; k0 += 64) {
#pragma unroll
        for (int i = 0; i < 8; i++) {
            int lin = tid + i * 256;
            int kk = lin & 63, rr = lin >> 6;
            int k = k0 + kk;
            z1s[rr * 65 + kk] = (k < H1) ? z1[(r0 + rr) * H1 + k] : 0.0f;
            w2s[rr * 65 + kk] = (k < H1) ? w2[rr * H1 + k] : 0.0f;   // rr == o row
        }
        __syncthreads();
#pragma unroll
        for (int kk = 0; kk < 64; kk++) {
            float wv = w2s[o * 65 + kk];
#pragma unroll
            for (int r = 0; r < 4; r++)
                acc[r] += z1s[(rg * 4 + r) * 65 + kk] * wv;
        }
        __syncthreads();
    }

    float bv = b2[o];
#pragma unroll
    for (int r = 0; r < 4; r++) {
        int b = r0 + rg * 4 + r;
        out[(size_t)head * BATCH * OUT_DIM + b * OUT_DIM + o] = tanhf(acc[r] + bv);
    }
}

// ---------------------------------------------------------------------------
// Launch
// ---------------------------------------------------------------------------
extern "C" void kernel_launch(void* const* d_in, const int* in_sizes, int n_in,
                              void* d_out, int out_size) {
    const float* x    = (const float*)d_in[0];
    const float* a    = (const float*)d_in[1];
    const float* m    = (const float*)d_in[2];
    const float* w_ih = (const float*)d_in[3];
    const float* w_hh = (const float*)d_in[4];
    const float* b_ih = (const float*)d_in[5];
    const float* b_hh = (const float*)d_in[6];
    const float* lw1  = (const float*)d_in[7];
    const float* lb1  = (const float*)d_in[8];
    const float* lw2  = (const float*)d_in[9];
    const float* lb2  = (const float*)d_in[10];
    const float* vw1  = (const float*)d_in[11];
    const float* vb1  = (const float*)d_in[12];
    const float* vw2  = (const float*)d_in[13];
    const float* vb2  = (const float*)d_in[14];

    zero_kernel<<<512, 256>>>();
    maxm_kernel<<<1, 256>>>(m);

    for (int s = 0; s < T_STEPS; s++)
        step_kernel<<<dim3(16, 16), 256>>>(x, a, w_ih, w_hh, b_ih, b_hh, s);

    mlp1_kernel<<<dim3(9, 16, 2), 256>>>(lw1, lb1, vw1, vb1);
    mlp2_kernel<<<dim3(32, 2), 256>>>(lw2, lb2, vw2, vb2, (float*)d_out);
}

// round 4
// speedup vs baseline: 1.0116x; 1.0116x over previous
#include <cuda_runtime.h>
#include <math.h>

// Problem constants
#define T_STEPS 200
#define BATCH   1024
#define XD      48
#define AD      15
#define IN_DIM  64      // XD + AD + 1
#define H_DIM   512
#define G4      2048    // 4*H
#define KTOT    576     // IN_DIM + H_DIM
#define OUT_DIM 32
#define H1      513     // H + 1

// Scratch (static device allocations only; no cudaMalloc anywhere)
__device__ float g_h[2][BATCH * H_DIM];   // double-buffered hidden state
__device__ float g_c[BATCH * H_DIM];      // cell state (tile-private, single buffer)
__device__ float g_z1[2][BATCH * H1];     // hidden of the two MLP heads
__device__ float g_maxm;

// ---------------------------------------------------------------------------
// Init: zero h[0] and c
// ---------------------------------------------------------------------------
__global__ __launch_bounds__(256) void zero_kernel() {
    int idx = blockIdx.x * blockDim.x + threadIdx.x;
    int stride = gridDim.x * blockDim.x;
    for (int i = idx; i < BATCH * H_DIM; i += stride) {
        g_h[0][i] = 0.0f;
        g_c[i]    = 0.0f;
    }
}

// ---------------------------------------------------------------------------
// max(m) over T*B elements — single CTA
// ---------------------------------------------------------------------------
__global__ __launch_bounds__(256) void maxm_kernel(const float* __restrict__ m) {
    __shared__ float red[256];
    float v = -1e30f;
    for (int i = threadIdx.x; i < T_STEPS * BATCH; i += 256)
        v = fmaxf(v, m[i]);
    red[threadIdx.x] = v;
    __syncthreads();
    for (int s = 128; s > 0; s >>= 1) {
        if (threadIdx.x < s) red[threadIdx.x] = fmaxf(red[threadIdx.x], red[threadIdx.x + s]);
        __syncthreads();
    }
    if (threadIdx.x == 0) g_maxm = red[0];
}

// ---------------------------------------------------------------------------
// Fused LSTM step: gates = x_in @ w_ih^T + h @ w_hh^T + (b_ih + b_hh),
// then cell update. CTA tile: 64 batch rows x 32 h-cols x all 4 gates
// (n_local = gate*32 + hc, 128 gate columns). One barrier-free fusion:
// i/f/g/o for a given (b,hc) live in the same thread's registers.
// ---------------------------------------------------------------------------
#define KC  32
#define SIS 65    // sIn row stride (conflict-free)
#define SWS 129   // sW row stride (conflict-free)

__global__ __launch_bounds__(256) void step_kernel(
    const float* __restrict__ x, const float* __restrict__ a,
    const float* __restrict__ w_ih, const float* __restrict__ w_hh,
    const float* __restrict__ b_ih, const float* __restrict__ b_hh,
    int s)
{
    __shared__ float sIn[KC * SIS];   // [k][b]  64 batch
    __shared__ float sW[KC * SWS];    // [k][n]  128 gate cols

    const int hT = blockIdx.x;            // 0..15  (32 h-cols each)
    const int bT = blockIdx.y;            // 0..15  (64 batch rows each)
    const int b0 = bT * 64;
    const int h0 = hT * 32;
    const int tid = threadIdx.x;
    const int tx = tid & 15;              // -> gate cols tx + 16*j
    const int ty = tid >> 4;              // -> batch rows ty + 16*i

    const float* __restrict__ hbuf = g_h[s & 1];
    float* __restrict__ hout       = g_h[(s + 1) & 1];
    const int trow = T_STEPS - 1 - s;     // flipped sequence index
    const float tval = (float)s / g_maxm;

    // Biases for this thread's 8 gate columns: n = gate*512 + h0 + tx + 16*m, j = 2*gate + m
    float bsum[8];
#pragma unroll
    for (int j = 0; j < 8; j++) {
        int n = (j >> 1) * H_DIM + h0 + tx + 16 * (j & 1);
        bsum[j] = b_ih[n] + b_hh[n];
    }

    float acc[4][8];
#pragma unroll
    for (int i = 0; i < 4; i++)
#pragma unroll
        for (int j = 0; j < 8; j++) acc[i][j] = 0.0f;

    for (int k0 = 0; k0 < KTOT; k0 += KC) {
        // Stage input tile [KC x 64]: warp lanes sweep kk (coalesced, conflict-free)
#pragma unroll
        for (int i = 0; i < 8; i++) {
            int lin = tid + i * 256;
            int kk = lin & 31, bb = lin >> 5;
            int kG = k0 + kk;
            int b = b0 + bb;
            float v;
            if (kG >= IN_DIM)           v = hbuf[b * H_DIM + (kG - IN_DIM)];
            else if (kG < XD)           v = x[(size_t)trow * BATCH * XD + b * XD + kG];
            else if (kG < XD + AD)      v = a[(size_t)trow * BATCH * AD + b * AD + (kG - XD)];
            else                        v = tval;
            sIn[kk * SIS + bb] = v;
        }
        // Stage weight tile [KC x 128]
#pragma unroll
        for (int i = 0; i < 16; i++) {
            int lin = tid + i * 256;
            int kk = lin & 31, nn = lin >> 5;
            int gate = nn >> 5, hc = nn & 31;
            int row = gate * H_DIM + h0 + hc;
            int kG = k0 + kk;
            float w = (kG < IN_DIM) ? w_ih[row * IN_DIM + kG]
                                    : w_hh[row * H_DIM + (kG - IN_DIM)];
            sW[kk * SWS + nn] = w;
        }
        __syncthreads();

#pragma unroll
        for (int k = 0; k < KC; k++) {
            float rIn[4], rW[8];
#pragma unroll
            for (int i = 0; i < 4; i++) rIn[i] = sIn[k * SIS + ty + 16 * i];
#pragma unroll
            for (int j = 0; j < 8; j++) rW[j] = sW[k * SWS + tx + 16 * j];
#pragma unroll
            for (int i = 0; i < 4; i++)
#pragma unroll
                for (int j = 0; j < 8; j++)
                    acc[i][j] += rIn[i] * rW[j];
        }
        __syncthreads();
    }

    // LSTM cell update — this thread owns gates (i,f,g,o) for rows b0+ty+16i,
    // h-cols h0+tx+16m:  gate index j = 2*gate + m.
#pragma unroll
    for (int i = 0; i < 4; i++) {
        int b = b0 + ty + 16 * i;
#pragma unroll
        for (int mm = 0; mm < 2; mm++) {
            int hc = h0 + tx + 16 * mm;
            float iv = acc[i][0 + mm] + bsum[0 + mm];
            float fv = acc[i][2 + mm] + bsum[2 + mm];
            float gv = acc[i][4 + mm] + bsum[4 + mm];
            float ov = acc[i][6 + mm] + bsum[6 + mm];
            iv = 1.0f / (1.0f + expf(-iv));
            fv = 1.0f / (1.0f + expf(-fv));
            ov = 1.0f / (1.0f + expf(-ov));
            gv = tanhf(gv);
            int idx = b * H_DIM + hc;
            float c = fv * g_c[idx] + iv * gv;
            g_c[idx] = c;
            hout[idx] = ov * tanhf(c);
        }
    }
}

// ---------------------------------------------------------------------------
// MLP layer 1: z1 = tanh(h_final @ w1^T + b1), two heads. M=1024, N=513, K=512.
// 64x64 tile, thread 4x4 microtile.
// ---------------------------------------------------------------------------
__global__ __launch_bounds__(256) void mlp1_kernel(
    const float* __restrict__ lw1, const float* __restrict__ lb1,
    const float* __restrict__ vw1, const float* __restrict__ vb1)
{
    __shared__ float sA[KC * SIS];       // [k][b]  64
    __shared__ float sW[KC * SIS];       // [k][n]  64 (same stride works)

    const int head = blockIdx.z;
    const float* __restrict__ w  = head ? vw1 : lw1;
    const float* __restrict__ b1 = head ? vb1 : lb1;
    const float* __restrict__ A  = g_h[0];        // s=199 wrote buffer 0
    float* __restrict__ z1 = g_z1[head];

    const int n0 = blockIdx.x * 64;
    const int b0 = blockIdx.y * 64;
    const int tid = threadIdx.x;
    const int tx = tid & 15, ty = tid >> 4;

    float acc[4][4];
#pragma unroll
    for (int i = 0; i < 4; i++)
#pragma unroll
        for (int j = 0; j < 4; j++) acc[i][j] = 0.0f;

    for (int k0 = 0; k0 < H_DIM; k0 += KC) {
#pragma unroll
        for (int i = 0; i < 8; i++) {
            int lin = tid + i * 256;
            int kk = lin & 31, bb = lin >> 5;
            sA[kk * SIS + bb] = A[(b0 + bb) * H_DIM + k0 + kk];
        }
#pragma unroll
        for (int i = 0; i < 8; i++) {
            int lin = tid + i * 256;
            int kk = lin & 31, nn = lin >> 5;
            int n = n0 + nn;
            sW[kk * SIS + nn] = (n < H1) ? w[n * H_DIM + k0 + kk] : 0.0f;
        }
        __syncthreads();
#pragma unroll
        for (int k = 0; k < KC; k++) {
            float rA[4], rW[4];
#pragma unroll
            for (int i = 0; i < 4; i++) rA[i] = sA[k * SIS + ty + 16 * i];
#pragma unroll
            for (int j = 0; j < 4; j++) rW[j] = sW[k * SIS + tx + 16 * j];
#pragma unroll
            for (int i = 0; i < 4; i++)
#pragma unroll
                for (int j = 0; j < 4; j++)
                    acc[i][j] += rA[i] * rW[j];
        }
        __syncthreads();
    }

#pragma unroll
    for (int j = 0; j < 4; j++) {
        int n = n0 + tx + 16 * j;
        if (n < H1) {
            float bv = b1[n];
#pragma unroll
            for (int i = 0; i < 4; i++) {
                int b = b0 + ty + 16 * i;
                z1[b * H1 + n] = tanhf(acc[i][j] + bv);
            }
        }
    }
}

// ---------------------------------------------------------------------------
// MLP layer 2: out = tanh(z1 @ w2^T + b2), two heads. M=1024, N=32, K=513.
// Block: 32 batch rows; thread = (o, row-group), smem-staged operands.
// ---------------------------------------------------------------------------
__global__ __launch_bounds__(256) void mlp2_kernel(
    const float* __restrict__ lw2, const float* __restrict__ lb2,
    const float* __restrict__ vw2, const float* __restrict__ vb2,
    float* __restrict__ out)
{
    __shared__ float z1s[32 * 65];  // [row][kk]
    __shared__ float w2s[32 * 65];  // [o][kk]

    const int head = blockIdx.y;
    const float* __restrict__ w2 = head ? vw2 : lw2;
    const float* __restrict__ b2 = head ? vb2 : lb2;
    const float* __restrict__ z1 = g_z1[head];

    const int r0 = blockIdx.x * 32;
    const int tid = threadIdx.x;
    const int o  = tid & 31;
    const int rg = tid >> 5;        // 0..7 -> rows rg*4 .. rg*4+3

    float acc[4] = {0.f, 0.f, 0.f, 0.f};

    for (int k0 = 0; k0 < H1; k0 += 64) {
#pragma unroll
        for (int i = 0; i < 8; i++) {
            int lin = tid + i * 256;
            int kk = lin & 63, rr = lin >> 6;
            int k = k0 + kk;
            z1s[rr * 65 + kk] = (k < H1) ? z1[(r0 + rr) * H1 + k] : 0.0f;
            w2s[rr * 65 + kk] = (k < H1) ? w2[rr * H1 + k] : 0.0f;   // rr == o row
        }
        __syncthreads();
#pragma unroll
        for (int kk = 0; kk < 64; kk++) {
            float wv = w2s[o * 65 + kk];
#pragma unroll
            for (int r = 0; r < 4; r++)
                acc[r] += z1s[(rg * 4 + r) * 65 + kk] * wv;
        }
        __syncthreads();
    }

    float bv = b2[o];
#pragma unroll
    for (int r = 0; r < 4; r++) {
        int b = r0 + rg * 4 + r;
        out[(size_t)head * BATCH * OUT_DIM + b * OUT_DIM + o] = tanhf(acc[r] + bv);
    }
}

// ---------------------------------------------------------------------------
// Launch
// ---------------------------------------------------------------------------
extern "C" void kernel_launch(void* const* d_in, const int* in_sizes, int n_in,
                              void* d_out, int out_size) {
    const float* x    = (const float*)d_in[0];
    const float* a    = (const float*)d_in[1];
    const float* m    = (const float*)d_in[2];
    const float* w_ih = (const float*)d_in[3];
    const float* w_hh = (const float*)d_in[4];
    const float* b_ih = (const float*)d_in[5];
    const float* b_hh = (const float*)d_in[6];
    const float* lw1  = (const float*)d_in[7];
    const float* lb1  = (const float*)d_in[8];
    const float* lw2  = (const float*)d_in[9];
    const float* lb2  = (const float*)d_in[10];
    const float* vw1  = (const float*)d_in[11];
    const float* vb1  = (const float*)d_in[12];
    const float* vw2  = (const float*)d_in[13];
    const float* vb2  = (const float*)d_in[14];

    zero_kernel<<<512, 256>>>();
    maxm_kernel<<<1, 256>>>(m);

    for (int s = 0; s < T_STEPS; s++)
        step_kernel<<<dim3(16, 16), 256>>>(x, a, w_ih, w_hh, b_ih, b_hh, s);

    mlp1_kernel<<<dim3(9, 16, 2), 256>>>(lw1, lb1, vw1, vb1);
    mlp2_kernel<<<dim3(32, 2), 256>>>(lw2, lb2, vw2, vb2, (float*)d_out);
}

// round 6
// speedup vs baseline: 3.1294x; 3.0936x over previous
#include <cuda_runtime.h>
#include <cuda_bf16.h>
#include <math.h>
#include <stdint.h>

#define T_STEPS 200
#define BATCH   1024
#define XD      48
#define AD      15
#define IN_DIM  64
#define H_DIM   512
#define OUT_DIM 32
#define H1      513
#define KTOT    1728       // 3*64 (x hi|lo|hi) + 3*512 (h hi|lo|hi)
#define CHUNKS  27         // KTOT / 64

// ---------------- static device scratch ----------------
__device__ __nv_bfloat16 g_Ax[T_STEPS][BATCH][192];   // [xhi|xlo|xhi] per step
__device__ __nv_bfloat16 g_Ah[2][BATCH][1536];        // [hhi|hlo|hhi] double buffered
__device__ __nv_bfloat16 g_W[2048][KTOT];             // permuted split weights
__device__ float g_bias[2048];                        // permuted b_ih+b_hh
__device__ float g_cpriv[128][256][16];               // c, CTA/thread-private layout
__device__ float g_hfinal[BATCH * H_DIM];
__device__ float g_z1[2][BATCH * H1];
__device__ float g_maxm;

// ---------------- helpers (sm_80-era only: cp.async, ldmatrix, mma.sync) ----
__device__ __forceinline__ uint32_t smem_u32(const void* p) {
    uint32_t a;
    asm("{ .reg .u64 t; cvta.to.shared.u64 t, %1; cvt.u32.u64 %0, t; }" : "=r"(a) : "l"(p));
    return a;
}
__device__ __forceinline__ uint32_t swz(uint32_t o) { return o ^ ((o >> 3) & 0x70); }
__device__ __forceinline__ void cpa16(uint32_t dst, const void* src) {
    asm volatile("cp.async.cg.shared.global [%0], [%1], 16;"
                 :: "r"(dst), "l"(__cvta_generic_to_global(src)));
}
__device__ __forceinline__ void ldsm4(uint32_t* r, uint32_t addr) {
    asm volatile("ldmatrix.sync.aligned.m8n8.x4.shared.b16 {%0,%1,%2,%3}, [%4];"
                 : "=r"(r[0]), "=r"(r[1]), "=r"(r[2]), "=r"(r[3]) : "r"(addr));
}
__device__ __forceinline__ void mma16816(float* d, const uint32_t* a, uint32_t b0, uint32_t b1) {
    asm volatile(
        "mma.sync.aligned.m16n8k16.row.col.f32.bf16.bf16.f32 "
        "{%0,%1,%2,%3},{%4,%5,%6,%7},{%8,%9},{%0,%1,%2,%3};"
        : "+f"(d[0]), "+f"(d[1]), "+f"(d[2]), "+f"(d[3])
        : "r"(a[0]), "r"(a[1]), "r"(a[2]), "r"(a[3]), "r"(b0), "r"(b1));
}

// ---------------- setup kernels ----------------
__global__ __launch_bounds__(256) void zero_kernel() {
    int idx = blockIdx.x * blockDim.x + threadIdx.x;
    int stride = gridDim.x * blockDim.x;
    __nv_bfloat16 z = __float2bfloat16(0.0f);
    for (int i = idx; i < BATCH * 1536; i += stride) (&g_Ah[0][0][0])[i] = z;
    for (int i = idx; i < 128 * 256 * 16; i += stride) (&g_cpriv[0][0][0])[i] = 0.0f;
}

__global__ __launch_bounds__(256) void maxm_kernel(const float* __restrict__ m) {
    __shared__ float red[256];
    float v = -1e30f;
    for (int i = threadIdx.x; i < T_STEPS * BATCH; i += 256) v = fmaxf(v, m[i]);
    red[threadIdx.x] = v;
    __syncthreads();
    for (int s = 128; s > 0; s >>= 1) {
        if (threadIdx.x < s) red[threadIdx.x] = fmaxf(red[threadIdx.x], red[threadIdx.x + s]);
        __syncthreads();
    }
    if (threadIdx.x == 0) g_maxm = red[0];
}

// Permuted split weights. np = hb*128 + gate*32 + hc  <->  r = gate*512 + hb*32 + hc
__global__ __launch_bounds__(256) void prep_w_kernel(
    const float* __restrict__ w_ih, const float* __restrict__ w_hh,
    const float* __restrict__ b_ih, const float* __restrict__ b_hh)
{
    int np = blockIdx.x;
    int hb = np >> 7;
    int gate = (np >> 5) & 3;
    int hc = np & 31;
    int r = gate * H_DIM + hb * 32 + hc;
    for (int k = threadIdx.x; k < KTOT; k += 256) {
        float v; bool lo;
        if (k < 192)        { v = w_ih[r * IN_DIM + (k & 63)]; lo = (k >= 128); }
        else if (k < 1216)  { v = w_hh[r * H_DIM + ((k - 192) & 511)]; lo = false; }
        else                { v = w_hh[r * H_DIM + (k - 1216)]; lo = true; }
        __nv_bfloat16 hi = __float2bfloat16(v);
        g_W[np][k] = lo ? __float2bfloat16(v - __bfloat162float(hi)) : hi;
    }
    if (threadIdx.x == 0) g_bias[np] = b_ih[r] + b_hh[r];
}

// x part of A for every step: [xhi | xlo | xhi]
__global__ __launch_bounds__(256) void prep_x_kernel(
    const float* __restrict__ x, const float* __restrict__ a)
{
    int s = blockIdx.x;
    int b = blockIdx.y * 4 + (threadIdx.x >> 6);
    int k = threadIdx.x & 63;
    int trow = T_STEPS - 1 - s;
    float v;
    if (k < XD)          v = x[((size_t)trow * BATCH + b) * XD + k];
    else if (k < 63)     v = a[((size_t)trow * BATCH + b) * AD + (k - XD)];
    else                 v = (float)s / g_maxm;
    __nv_bfloat16 hi = __float2bfloat16(v);
    __nv_bfloat16 lo = __float2bfloat16(v - __bfloat162float(hi));
    g_Ax[s][b][k]       = hi;
    g_Ax[s][b][64 + k]  = lo;
    g_Ax[s][b][128 + k] = hi;
}

// ---------------- mma.sync LSTM step ----------------
#define STAGE_BYTES 32768                // A 16KB + B 16KB
#define SMEM_REQ (1024 + 2 * STAGE_BYTES + 512)

__global__ void __launch_bounds__(256, 1) step_kernel(int s)
{
    extern __shared__ char smraw[];
    char* sm = (char*)(((uintptr_t)smraw + 1023) & ~(uintptr_t)1023);
    uint32_t sb = smem_u32(sm);

    const int tid = threadIdx.x;
    const int wid = tid >> 5, lane = tid & 31;
    const int nT = blockIdx.x;           // 0..15: h-block (32 hc x 4 gates)
    const int mT = blockIdx.y;           // 0..7:  128 batch rows

    float* sBias = (float*)(sm + 2 * STAGE_BYTES);
    if (tid < 128) sBias[tid] = g_bias[nT * 128 + tid];

    const __nv_bfloat16* __restrict__ Ax = &g_Ax[s][mT * 128][0];       // stride 192
    const __nv_bfloat16* __restrict__ Ah = &g_Ah[s & 1][mT * 128][0];   // stride 1536
    const __nv_bfloat16* __restrict__ W  = &g_W[nT * 128][0];           // stride KTOT

    // ---- async stage of chunk j into buffer j&1 ----
    auto issue = [&](int j) {
        uint32_t base = sb + (j & 1) * STAGE_BYTES;
#pragma unroll
        for (int o = 0; o < 8; o++) {
            int lin = o * 256 + tid;
            const void* src;
            uint32_t dst;
            if (lin < 1024) {                      // A tile: 128 rows x 128B
                int row = lin >> 3, c16 = lin & 7;
                src = (j < 3) ? (const void*)(Ax + (size_t)row * 192 + j * 64 + c16 * 8)
                              : (const void*)(Ah + (size_t)row * 1536 + (j - 3) * 64 + c16 * 8);
                dst = base + swz(row * 128 + c16 * 16);
            } else {                               // B tile: 128 rows x 128B
                int l2 = lin - 1024;
                int row = l2 >> 3, c16 = l2 & 7;
                src = (const void*)(W + (size_t)row * KTOT + j * 64 + c16 * 8);
                dst = base + 16384 + swz(row * 128 + c16 * 16);
            }
            cpa16(dst, src);
        }
        asm volatile("cp.async.commit_group;" ::: "memory");
    };

    float acc[16][4];                    // 16 n-tiles (8 cols each) x 4
#pragma unroll
    for (int nt = 0; nt < 16; nt++)
#pragma unroll
        for (int q = 0; q < 4; q++) acc[nt][q] = 0.0f;

    // ldmatrix address components (identical pattern for A and B)
    const int lrow = lane & 15;
    const uint32_t lcol = (lane >> 4) * 16;

    issue(0);
    for (int j = 0; j < CHUNKS; j++) {
        if (j + 1 < CHUNKS) {
            issue(j + 1);
            asm volatile("cp.async.wait_group 1;" ::: "memory");
        } else {
            asm volatile("cp.async.wait_group 0;" ::: "memory");
        }
        __syncthreads();

        uint32_t Abase = sb + (j & 1) * STAGE_BYTES;
        uint32_t Bbase = Abase + 16384;
#pragma unroll
        for (int ks = 0; ks < 4; ks++) {
            uint32_t a[4];
            ldsm4(a, Abase + swz((wid * 16 + lrow) * 128 + ks * 32 + lcol));
#pragma unroll
            for (int nb = 0; nb < 8; nb++) {
                uint32_t b[4];
                ldsm4(b, Bbase + swz((nb * 16 + lrow) * 128 + ks * 32 + lcol));
                mma16816(acc[nb * 2 + 0], a, b[0], b[2]);
                mma16816(acc[nb * 2 + 1], a, b[1], b[3]);
            }
        }
        __syncthreads();
    }

    // ---------- epilogue: fused cell update (all in registers) ----------
    // warp w rows: w*16 + (lane>>2) and +8.  acc[gate*4+jj][rh*2+t] is
    // col = gate*32 + jj*8 + 2*(lane&3) + t  ->  gate g, hc = jj*8+2*(lane&3)+t
    const int cta = mT * 16 + nT;
    float* __restrict__ cpr = &g_cpriv[cta][tid][0];
    float cv[16];
#pragma unroll
    for (int q = 0; q < 4; q++) {
        float4 t4 = ((const float4*)cpr)[q];
        cv[q * 4] = t4.x; cv[q * 4 + 1] = t4.y; cv[q * 4 + 2] = t4.z; cv[q * 4 + 3] = t4.w;
    }

    float* sH = (float*)sm;              // reuse stage area: [128][33]
#pragma unroll
    for (int rh = 0; rh < 2; rh++) {
        int row = wid * 16 + (lane >> 2) + rh * 8;
#pragma unroll
        for (int jj = 0; jj < 4; jj++) {
#pragma unroll
            for (int t = 0; t < 2; t++) {
                int hc = jj * 8 + 2 * (lane & 3) + t;
                int e = rh * 8 + jj * 2 + t;
                float iv = acc[0 * 4 + jj][rh * 2 + t] + sBias[0 + hc];
                float fv = acc[1 * 4 + jj][rh * 2 + t] + sBias[32 + hc];
                float gv = acc[2 * 4 + jj][rh * 2 + t] + sBias[64 + hc];
                float ov = acc[3 * 4 + jj][rh * 2 + t] + sBias[96 + hc];
                iv = 1.0f / (1.0f + expf(-iv));
                fv = 1.0f / (1.0f + expf(-fv));
                ov = 1.0f / (1.0f + expf(-ov));
                gv = tanhf(gv);
                float c = fv * cv[e] + iv * gv;
                cv[e] = c;
                sH[row * 33 + hc] = ov * tanhf(c);
            }
        }
    }
#pragma unroll
    for (int q = 0; q < 4; q++) {
        float4 t4;
        t4.x = cv[q * 4]; t4.y = cv[q * 4 + 1]; t4.z = cv[q * 4 + 2]; t4.w = cv[q * 4 + 3];
        ((float4*)cpr)[q] = t4;
    }
    __syncthreads();

    // coalesced h write: next step's A operand (bf16 hi|lo|hi) [+ fp32 final]
    {
        const int r = tid >> 1, hc0 = (tid & 1) * 16;
        const int m = mT * 128 + r;
        __nv_bfloat16 hi[16], lo[16];
        float hv[16];
#pragma unroll
        for (int i = 0; i < 16; i++) {
            hv[i] = sH[r * 33 + hc0 + i];
            __nv_bfloat16 h = __float2bfloat16(hv[i]);
            hi[i] = h;
            lo[i] = __float2bfloat16(hv[i] - __bfloat162float(h));
        }
        __nv_bfloat16* Aout = &g_Ah[(s + 1) & 1][0][0];
        size_t basei = (size_t)m * 1536 + nT * 32 + hc0;
        uint4* vh = (uint4*)hi;
        uint4* vl = (uint4*)lo;
        ((uint4*)&Aout[basei])[0] = vh[0];        ((uint4*)&Aout[basei])[1] = vh[1];
        ((uint4*)&Aout[basei + 512])[0] = vl[0];  ((uint4*)&Aout[basei + 512])[1] = vl[1];
        ((uint4*)&Aout[basei + 1024])[0] = vh[0]; ((uint4*)&Aout[basei + 1024])[1] = vh[1];
        if (s == T_STEPS - 1) {
            float4* pf = (float4*)&g_hfinal[(size_t)m * H_DIM + nT * 32 + hc0];
#pragma unroll
            for (int q = 0; q < 4; q++) {
                float4 t4;
                t4.x = hv[q * 4]; t4.y = hv[q * 4 + 1]; t4.z = hv[q * 4 + 2]; t4.w = hv[q * 4 + 3];
                pf[q] = t4;
            }
        }
    }
}

// ---------------- MLP heads ----------------
#define KCM 32
#define SIS 65
__global__ __launch_bounds__(256) void mlp1_kernel(
    const float* __restrict__ lw1, const float* __restrict__ lb1,
    const float* __restrict__ vw1, const float* __restrict__ vb1)
{
    __shared__ float sA[KCM * SIS];
    __shared__ float sW[KCM * SIS];
    const int head = blockIdx.z;
    const float* __restrict__ w  = head ? vw1 : lw1;
    const float* __restrict__ b1 = head ? vb1 : lb1;
    const float* __restrict__ A  = g_hfinal;
    float* __restrict__ z1 = g_z1[head];
    const int n0 = blockIdx.x * 64, b0 = blockIdx.y * 64;
    const int tid = threadIdx.x, tx = tid & 15, ty = tid >> 4;
    float acc[4][4];
#pragma unroll
    for (int i = 0; i < 4; i++)
#pragma unroll
        for (int j = 0; j < 4; j++) acc[i][j] = 0.0f;
    for (int k0 = 0; k0 < H_DIM; k0 += KCM) {
#pragma unroll
        for (int i = 0; i < 8; i++) {
            int lin = tid + i * 256;
            int kk = lin & 31, bb = lin >> 5;
            sA[kk * SIS + bb] = A[(b0 + bb) * H_DIM + k0 + kk];
        }
#pragma unroll
        for (int i = 0; i < 8; i++) {
            int lin = tid + i * 256;
            int kk = lin & 31, nn = lin >> 5;
            int n = n0 + nn;
            sW[kk * SIS + nn] = (n < H1) ? w[n * H_DIM + k0 + kk] : 0.0f;
        }
        __syncthreads();
#pragma unroll
        for (int k = 0; k < KCM; k++) {
            float rA[4], rW[4];
#pragma unroll
            for (int i = 0; i < 4; i++) rA[i] = sA[k * SIS + ty + 16 * i];
#pragma unroll
            for (int j = 0; j < 4; j++) rW[j] = sW[k * SIS + tx + 16 * j];
#pragma unroll
            for (int i = 0; i < 4; i++)
#pragma unroll
                for (int j = 0; j < 4; j++) acc[i][j] += rA[i] * rW[j];
        }
        __syncthreads();
    }
#pragma unroll
    for (int j = 0; j < 4; j++) {
        int n = n0 + tx + 16 * j;
        if (n < H1) {
            float bv = b1[n];
#pragma unroll
            for (int i = 0; i < 4; i++)
                z1[(b0 + ty + 16 * i) * H1 + n] = tanhf(acc[i][j] + bv);
        }
    }
}

__global__ __launch_bounds__(256) void mlp2_kernel(
    const float* __restrict__ lw2, const float* __restrict__ lb2,
    const float* __restrict__ vw2, const float* __restrict__ vb2,
    float* __restrict__ out)
{
    __shared__ float z1s[32 * 65];
    __shared__ float w2s[32 * 65];
    const int head = blockIdx.y;
    const float* __restrict__ w2 = head ? vw2 : lw2;
    const float* __restrict__ b2 = head ? vb2 : lb2;
    const float* __restrict__ z1 = g_z1[head];
    const int r0 = blockIdx.x * 32;
    const int tid = threadIdx.x, o = tid & 31, rg = tid >> 5;
    float acc[4] = {0.f, 0.f, 0.f, 0.f};
    for (int k0 = 0; k0 < H1; k0 += 64) {
#pragma unroll
        for (int i = 0; i < 8; i++) {
            int lin = tid + i * 256;
            int kk = lin & 63, rr = lin >> 6;
            int k = k0 + kk;
            z1s[rr * 65 + kk] = (k < H1) ? z1[(r0 + rr) * H1 + k] : 0.0f;
            w2s[rr * 65 + kk] = (k < H1) ? w2[rr * H1 + k] : 0.0f;
        }
        __syncthreads();
#pragma unroll
        for (int kk = 0; kk < 64; kk++) {
            float wv = w2s[o * 65 + kk];
#pragma unroll
            for (int r = 0; r < 4; r++) acc[r] += z1s[(rg * 4 + r) * 65 + kk] * wv;
        }
        __syncthreads();
    }
    float bv = b2[o];
#pragma unroll
    for (int r = 0; r < 4; r++)
        out[(size_t)head * BATCH * OUT_DIM + (r0 + rg * 4 + r) * OUT_DIM + o] = tanhf(acc[r] + bv);
}

// ---------------- launch ----------------
extern "C" void kernel_launch(void* const* d_in, const int* in_sizes, int n_in,
                              void* d_out, int out_size) {
    const float* x    = (const float*)d_in[0];
    const float* a    = (const float*)d_in[1];
    const float* m    = (const float*)d_in[2];
    const float* w_ih = (const float*)d_in[3];
    const float* w_hh = (const float*)d_in[4];
    const float* b_ih = (const float*)d_in[5];
    const float* b_hh = (const float*)d_in[6];
    const float* lw1  = (const float*)d_in[7];
    const float* lb1  = (const float*)d_in[8];
    const float* lw2  = (const float*)d_in[9];
    const float* lb2  = (const float*)d_in[10];
    const float* vw1  = (const float*)d_in[11];
    const float* vb1  = (const float*)d_in[12];
    const float* vw2  = (const float*)d_in[13];
    const float* vb2  = (const float*)d_in[14];

    cudaFuncSetAttribute(step_kernel, cudaFuncAttributeMaxDynamicSharedMemorySize, SMEM_REQ);

    zero_kernel<<<512, 256>>>();
    maxm_kernel<<<1, 256>>>(m);
    prep_w_kernel<<<2048, 256>>>(w_ih, w_hh, b_ih, b_hh);
    prep_x_kernel<<<dim3(T_STEPS, BATCH / 4), 256>>>(x, a);

    for (int s = 0; s < T_STEPS; s++)
        step_kernel<<<dim3(16, 8), 256, SMEM_REQ>>>(s);

    mlp1_kernel<<<dim3(9, 16, 2), 256>>>(lw1, lb1, vw1, vb1);
    mlp2_kernel<<<dim3(32, 2), 256>>>(lw2, lb2, vw2, vb2, (float*)d_out);
}

// round 7
// speedup vs baseline: 4.3561x; 1.3920x over previous
#include <cuda_runtime.h>
#include <cuda_fp16.h>
#include <math.h>
#include <stdint.h>

#define T_STEPS 200
#define BATCH   1024
#define XD      48
#define AD      15
#define IN_DIM  64
#define H_DIM   512
#define OUT_DIM 32
#define H1      513
#define KTOT    1152       // 2*64 (x hi|lo) + 2*512 (h hi|lo)
#define CHUNKS  18         // KTOT / 64

// ---------------- static device scratch ----------------
__device__ __half g_Ax[T_STEPS][BATCH][128];   // [xhi|xlo] per step
__device__ __half g_Ah[2][BATCH][1024];        // [hhi|hlo] double buffered
__device__ __half g_W[2048][KTOT];             // permuted weights [Whi|Whi|Whi|Whi] blocks
__device__ float g_bias[2048];                 // permuted b_ih+b_hh
__device__ float g_cpriv[128][256][16];        // c, CTA/thread-private layout
__device__ float g_hfinal[BATCH * H_DIM];
__device__ float g_z1[2][BATCH * H1];
__device__ float g_maxm;

// ---------------- helpers (sm_80-era: cp.async, ldmatrix, mma.sync) --------
__device__ __forceinline__ uint32_t smem_u32(const void* p) {
    uint32_t a;
    asm("{ .reg .u64 t; cvta.to.shared.u64 t, %1; cvt.u32.u64 %0, t; }" : "=r"(a) : "l"(p));
    return a;
}
__device__ __forceinline__ uint32_t swz(uint32_t o) { return o ^ ((o >> 3) & 0x70); }
__device__ __forceinline__ void cpa16(uint32_t dst, const void* src) {
    asm volatile("cp.async.cg.shared.global [%0], [%1], 16;"
                 :: "r"(dst), "l"(__cvta_generic_to_global(src)));
}
__device__ __forceinline__ void ldsm4(uint32_t* r, uint32_t addr) {
    asm volatile("ldmatrix.sync.aligned.m8n8.x4.shared.b16 {%0,%1,%2,%3}, [%4];"
                 : "=r"(r[0]), "=r"(r[1]), "=r"(r[2]), "=r"(r[3]) : "r"(addr));
}
__device__ __forceinline__ void mma16816(float* d, const uint32_t* a, uint32_t b0, uint32_t b1) {
    asm volatile(
        "mma.sync.aligned.m16n8k16.row.col.f32.f16.f16.f32 "
        "{%0,%1,%2,%3},{%4,%5,%6,%7},{%8,%9},{%0,%1,%2,%3};"
        : "+f"(d[0]), "+f"(d[1]), "+f"(d[2]), "+f"(d[3])
        : "r"(a[0]), "r"(a[1]), "r"(a[2]), "r"(a[3]), "r"(b0), "r"(b1));
}

// ---------------- setup kernels ----------------
__global__ __launch_bounds__(256) void zero_kernel() {
    int idx = blockIdx.x * blockDim.x + threadIdx.x;
    int stride = gridDim.x * blockDim.x;
    __half z = __float2half(0.0f);
    for (int i = idx; i < BATCH * 1024; i += stride) (&g_Ah[0][0][0])[i] = z;
    for (int i = idx; i < 128 * 256 * 16; i += stride) (&g_cpriv[0][0][0])[i] = 0.0f;
}

__global__ __launch_bounds__(256) void maxm_kernel(const float* __restrict__ m) {
    __shared__ float red[256];
    float v = -1e30f;
    for (int i = threadIdx.x; i < T_STEPS * BATCH; i += 256) v = fmaxf(v, m[i]);
    red[threadIdx.x] = v;
    __syncthreads();
    for (int s = 128; s > 0; s >>= 1) {
        if (threadIdx.x < s) red[threadIdx.x] = fmaxf(red[threadIdx.x], red[threadIdx.x + s]);
        __syncthreads();
    }
    if (threadIdx.x == 0) g_maxm = red[0];
}

// Permuted weights (all fp16 hi). np = hb*128 + gate*32 + hc  <->  r = gate*512 + hb*32 + hc
// K layout matches A: [Wih | Wih | Whh | Whh]  (hi duplicated for the lo cross term)
__global__ __launch_bounds__(256) void prep_w_kernel(
    const float* __restrict__ w_ih, const float* __restrict__ w_hh,
    const float* __restrict__ b_ih, const float* __restrict__ b_hh)
{
    int np = blockIdx.x;
    int hb = np >> 7;
    int gate = (np >> 5) & 3;
    int hc = np & 31;
    int r = gate * H_DIM + hb * 32 + hc;
    for (int k = threadIdx.x; k < KTOT; k += 256) {
        float v;
        if (k < 128)       v = w_ih[r * IN_DIM + (k & 63)];
        else               v = w_hh[r * H_DIM + ((k - 128) & 511)];
        g_W[np][k] = __float2half(v);
    }
    if (threadIdx.x == 0) g_bias[np] = b_ih[r] + b_hh[r];
}

// x part of A for every step: [xhi | xlo]
__global__ __launch_bounds__(256) void prep_x_kernel(
    const float* __restrict__ x, const float* __restrict__ a)
{
    int s = blockIdx.x;
    int b = blockIdx.y * 4 + (threadIdx.x >> 6);
    int k = threadIdx.x & 63;
    int trow = T_STEPS - 1 - s;
    float v;
    if (k < XD)          v = x[((size_t)trow * BATCH + b) * XD + k];
    else if (k < 63)     v = a[((size_t)trow * BATCH + b) * AD + (k - XD)];
    else                 v = (float)s / g_maxm;
    __half hi = __float2half(v);
    __half lo = __float2half(v - __half2float(hi));
    g_Ax[s][b][k]      = hi;
    g_Ax[s][b][64 + k] = lo;
}

// ---------------- mma.sync LSTM step (3-stage pipeline) ----------------
#define STAGE_BYTES 32768                // A 16KB + B 16KB
#define NSTAGE 3
#define SMEM_REQ (1024 + NSTAGE * STAGE_BYTES + 512)

__global__ void __launch_bounds__(256, 1) step_kernel(int s)
{
    extern __shared__ char smraw[];
    char* sm = (char*)(((uintptr_t)smraw + 1023) & ~(uintptr_t)1023);
    uint32_t sb = smem_u32(sm);

    const int tid = threadIdx.x;
    const int wid = tid >> 5, lane = tid & 31;
    const int nT = blockIdx.x;           // 0..15: h-block (32 hc x 4 gates)
    const int mT = blockIdx.y;           // 0..7:  128 batch rows

    float* sBias = (float*)(sm + NSTAGE * STAGE_BYTES);
    if (tid < 128) sBias[tid] = g_bias[nT * 128 + tid];

    const __half* __restrict__ Ax = &g_Ax[s][mT * 128][0];       // stride 128
    const __half* __restrict__ Ah = &g_Ah[s & 1][mT * 128][0];   // stride 1024
    const __half* __restrict__ W  = &g_W[nT * 128][0];           // stride KTOT

    auto issue = [&](int j) {
        uint32_t base = sb + (j % NSTAGE) * STAGE_BYTES;
#pragma unroll
        for (int o = 0; o < 8; o++) {
            int lin = o * 256 + tid;
            const void* src;
            uint32_t dst;
            if (lin < 1024) {                      // A tile: 128 rows x 128B
                int row = lin >> 3, c16 = lin & 7;
                src = (j < 2) ? (const void*)(Ax + (size_t)row * 128 + j * 64 + c16 * 8)
                              : (const void*)(Ah + (size_t)row * 1024 + (j - 2) * 64 + c16 * 8);
                dst = base + swz(row * 128 + c16 * 16);
            } else {                               // B tile: 128 rows x 128B
                int l2 = lin - 1024;
                int row = l2 >> 3, c16 = l2 & 7;
                src = (const void*)(W + (size_t)row * KTOT + j * 64 + c16 * 8);
                dst = base + 16384 + swz(row * 128 + c16 * 16);
            }
            cpa16(dst, src);
        }
        asm volatile("cp.async.commit_group;" ::: "memory");
    };

    float acc[16][4];
#pragma unroll
    for (int nt = 0; nt < 16; nt++)
#pragma unroll
        for (int q = 0; q < 4; q++) acc[nt][q] = 0.0f;

    const int lrow = lane & 15;
    const uint32_t lcol = (lane >> 4) * 16;

    issue(0);
    issue(1);
    for (int j = 0; j < CHUNKS; j++) {
        if (j + 2 < CHUNKS) {
            issue(j + 2);
            asm volatile("cp.async.wait_group 2;" ::: "memory");
        } else if (j + 1 < CHUNKS) {
            asm volatile("cp.async.wait_group 1;" ::: "memory");
        } else {
            asm volatile("cp.async.wait_group 0;" ::: "memory");
        }
        __syncthreads();

        uint32_t Abase = sb + (j % NSTAGE) * STAGE_BYTES;
        uint32_t Bbase = Abase + 16384;
#pragma unroll
        for (int ks = 0; ks < 4; ks++) {
            uint32_t a[4];
            ldsm4(a, Abase + swz((wid * 16 + lrow) * 128 + ks * 32 + lcol));
#pragma unroll
            for (int nb = 0; nb < 8; nb++) {
                uint32_t b[4];
                ldsm4(b, Bbase + swz((nb * 16 + lrow) * 128 + ks * 32 + lcol));
                mma16816(acc[nb * 2 + 0], a, b[0], b[2]);
                mma16816(acc[nb * 2 + 1], a, b[1], b[3]);
            }
        }
        __syncthreads();
    }

    // ---------- epilogue: fused cell update (registers) ----------
    const int cta = mT * 16 + nT;
    float* __restrict__ cpr = &g_cpriv[cta][tid][0];
    float cv[16];
#pragma unroll
    for (int q = 0; q < 4; q++) {
        float4 t4 = ((const float4*)cpr)[q];
        cv[q * 4] = t4.x; cv[q * 4 + 1] = t4.y; cv[q * 4 + 2] = t4.z; cv[q * 4 + 3] = t4.w;
    }

    float* sH = (float*)sm;              // reuse stage area: [128][33]
#pragma unroll
    for (int rh = 0; rh < 2; rh++) {
        int row = wid * 16 + (lane >> 2) + rh * 8;
#pragma unroll
        for (int jj = 0; jj < 4; jj++) {
#pragma unroll
            for (int t = 0; t < 2; t++) {
                int hc = jj * 8 + 2 * (lane & 3) + t;
                int e = rh * 8 + jj * 2 + t;
                float iv = acc[0 * 4 + jj][rh * 2 + t] + sBias[0 + hc];
                float fv = acc[1 * 4 + jj][rh * 2 + t] + sBias[32 + hc];
                float gv = acc[2 * 4 + jj][rh * 2 + t] + sBias[64 + hc];
                float ov = acc[3 * 4 + jj][rh * 2 + t] + sBias[96 + hc];
                iv = 1.0f / (1.0f + expf(-iv));
                fv = 1.0f / (1.0f + expf(-fv));
                ov = 1.0f / (1.0f + expf(-ov));
                gv = tanhf(gv);
                float c = fv * cv[e] + iv * gv;
                cv[e] = c;
                sH[row * 33 + hc] = ov * tanhf(c);
            }
        }
    }
#pragma unroll
    for (int q = 0; q < 4; q++) {
        float4 t4;
        t4.x = cv[q * 4]; t4.y = cv[q * 4 + 1]; t4.z = cv[q * 4 + 2]; t4.w = cv[q * 4 + 3];
        ((float4*)cpr)[q] = t4;
    }
    __syncthreads();

    // coalesced h write: next step's A operand (fp16 hi|lo) [+ fp32 final]
    {
        const int r = tid >> 1, hc0 = (tid & 1) * 16;
        const int m = mT * 128 + r;
        __half hi[16], lo[16];
        float hv[16];
#pragma unroll
        for (int i = 0; i < 16; i++) {
            hv[i] = sH[r * 33 + hc0 + i];
            __half h = __float2half(hv[i]);
            hi[i] = h;
            lo[i] = __float2half(hv[i] - __half2float(h));
        }
        __half* Aout = &g_Ah[(s + 1) & 1][0][0];
        size_t basei = (size_t)m * 1024 + nT * 32 + hc0;
        uint4* vh = (uint4*)hi;
        uint4* vl = (uint4*)lo;
        ((uint4*)&Aout[basei])[0] = vh[0];       ((uint4*)&Aout[basei])[1] = vh[1];
        ((uint4*)&Aout[basei + 512])[0] = vl[0]; ((uint4*)&Aout[basei + 512])[1] = vl[1];
        if (s == T_STEPS - 1) {
            float4* pf = (float4*)&g_hfinal[(size_t)m * H_DIM + nT * 32 + hc0];
#pragma unroll
            for (int q = 0; q < 4; q++) {
                float4 t4;
                t4.x = hv[q * 4]; t4.y = hv[q * 4 + 1]; t4.z = hv[q * 4 + 2]; t4.w = hv[q * 4 + 3];
                pf[q] = t4;
            }
        }
    }
}

// ---------------- MLP heads ----------------
#define KCM 32
#define SIS 65
__global__ __launch_bounds__(256) void mlp1_kernel(
    const float* __restrict__ lw1, const float* __restrict__ lb1,
    const float* __restrict__ vw1, const float* __restrict__ vb1)
{
    __shared__ float sA[KCM * SIS];
    __shared__ float sW[KCM * SIS];
    const int head = blockIdx.z;
    const float* __restrict__ w  = head ? vw1 : lw1;
    const float* __restrict__ b1 = head ? vb1 : lb1;
    const float* __restrict__ A  = g_hfinal;
    float* __restrict__ z1 = g_z1[head];
    const int n0 = blockIdx.x * 64, b0 = blockIdx.y * 64;
    const int tid = threadIdx.x, tx = tid & 15, ty = tid >> 4;
    float acc[4][4];
#pragma unroll
    for (int i = 0; i < 4; i++)
#pragma unroll
        for (int j = 0; j < 4; j++) acc[i][j] = 0.0f;
    for (int k0 = 0; k0 < H_DIM; k0 += KCM) {
#pragma unroll
        for (int i = 0; i < 8; i++) {
            int lin = tid + i * 256;
            int kk = lin & 31, bb = lin >> 5;
            sA[kk * SIS + bb] = A[(b0 + bb) * H_DIM + k0 + kk];
        }
#pragma unroll
        for (int i = 0; i < 8; i++) {
            int lin = tid + i * 256;
            int kk = lin & 31, nn = lin >> 5;
            int n = n0 + nn;
            sW[kk * SIS + nn] = (n < H1) ? w[n * H_DIM + k0 + kk] : 0.0f;
        }
        __syncthreads();
#pragma unroll
        for (int k = 0; k < KCM; k++) {
            float rA[4], rW[4];
#pragma unroll
            for (int i = 0; i < 4; i++) rA[i] = sA[k * SIS + ty + 16 * i];
#pragma unroll
            for (int j = 0; j < 4; j++) rW[j] = sW[k * SIS + tx + 16 * j];
#pragma unroll
            for (int i = 0; i < 4; i++)
#pragma unroll
                for (int j = 0; j < 4; j++) acc[i][j] += rA[i] * rW[j];
        }
        __syncthreads();
    }
#pragma unroll
    for (int j = 0; j < 4; j++) {
        int n = n0 + tx + 16 * j;
        if (n < H1) {
            float bv = b1[n];
#pragma unroll
            for (int i = 0; i < 4; i++)
                z1[(b0 + ty + 16 * i) * H1 + n] = tanhf(acc[i][j] + bv);
        }
    }
}

__global__ __launch_bounds__(256) void mlp2_kernel(
    const float* __restrict__ lw2, const float* __restrict__ lb2,
    const float* __restrict__ vw2, const float* __restrict__ vb2,
    float* __restrict__ out)
{
    __shared__ float z1s[32 * 65];
    __shared__ float w2s[32 * 65];
    const int head = blockIdx.y;
    const float* __restrict__ w2 = head ? vw2 : lw2;
    const float* __restrict__ b2 = head ? vb2 : lb2;
    const float* __restrict__ z1 = g_z1[head];
    const int r0 = blockIdx.x * 32;
    const int tid = threadIdx.x, o = tid & 31, rg = tid >> 5;
    float acc[4] = {0.f, 0.f, 0.f, 0.f};
    for (int k0 = 0; k0 < H1; k0 += 64) {
#pragma unroll
        for (int i = 0; i < 8; i++) {
            int lin = tid + i * 256;
            int kk = lin & 63, rr = lin >> 6;
            int k = k0 + kk;
            z1s[rr * 65 + kk] = (k < H1) ? z1[(r0 + rr) * H1 + k] : 0.0f;
            w2s[rr * 65 + kk] = (k < H1) ? w2[rr * H1 + k] : 0.0f;
        }
        __syncthreads();
#pragma unroll
        for (int kk = 0; kk < 64; kk++) {
            float wv = w2s[o * 65 + kk];
#pragma unroll
            for (int r = 0; r < 4; r++) acc[r] += z1s[(rg * 4 + r) * 65 + kk] * wv;
        }
        __syncthreads();
    }
    float bv = b2[o];
#pragma unroll
    for (int r = 0; r < 4; r++)
        out[(size_t)head * BATCH * OUT_DIM + (r0 + rg * 4 + r) * OUT_DIM + o] = tanhf(acc[r] + bv);
}

// ---------------- launch ----------------
extern "C" void kernel_launch(void* const* d_in, const int* in_sizes, int n_in,
                              void* d_out, int out_size) {
    const float* x    = (const float*)d_in[0];
    const float* a    = (const float*)d_in[1];
    const float* m    = (const float*)d_in[2];
    const float* w_ih = (const float*)d_in[3];
    const float* w_hh = (const float*)d_in[4];
    const float* b_ih = (const float*)d_in[5];
    const float* b_hh = (const float*)d_in[6];
    const float* lw1  = (const float*)d_in[7];
    const float* lb1  = (const float*)d_in[8];
    const float* lw2  = (const float*)d_in[9];
    const float* lb2  = (const float*)d_in[10];
    const float* vw1  = (const float*)d_in[11];
    const float* vb1  = (const float*)d_in[12];
    const float* vw2  = (const float*)d_in[13];
    const float* vb2  = (const float*)d_in[14];

    cudaFuncSetAttribute(step_kernel, cudaFuncAttributeMaxDynamicSharedMemorySize, SMEM_REQ);

    zero_kernel<<<512, 256>>>();
    maxm_kernel<<<1, 256>>>(m);
    prep_w_kernel<<<2048, 256>>>(w_ih, w_hh, b_ih, b_hh);
    prep_x_kernel<<<dim3(T_STEPS, BATCH / 4), 256>>>(x, a);

    for (int s = 0; s < T_STEPS; s++)
        step_kernel<<<dim3(16, 8), 256, SMEM_REQ>>>(s);

    mlp1_kernel<<<dim3(9, 16, 2), 256>>>(lw1, lb1, vw1, vb1);
    mlp2_kernel<<<dim3(32, 2), 256>>>(lw2, lb2, vw2, vb2, (float*)d_out);
}